// round 13
// baseline (speedup 1.0000x reference)
#include <cuda_runtime.h>
#include <cuda_fp16.h>
#include <cstdint>

#define NN 10000
#define TT 24
#define NE 320000
#define HH 64
#define G4 256   // 4*H
#define FULL 0xffffffffu

// ---------------- scratch ----------------
__device__ __half2 g_Hh[(size_t)TT * NN * 32];   // h * norm_src, fp16, per t
__device__ __half2 g_Zh[(size_t)TT * NN * 32];   // z0 * norm_src, fp16, per t
__device__ float   g_P[(size_t)NN * TT + 32];    // (z1*norm_src) . Wg2, [node][t]
__device__ int     g_deg_out[NN];
__device__ int     g_deg_in[NN];
__device__ int     g_cursor[NN];
__device__ int     g_offs[NN + 1];
__device__ int     g_csr[NE];                    // src indices grouped by dst
__device__ float   g_nsrc[NN];
__device__ float   g_ndst[NN];

// ---------------- helpers ----------------
__device__ __forceinline__ float tanh_fast(float x) {
    float y;
    asm("tanh.approx.f32 %0, %1;" : "=f"(y) : "f"(x));
    return y;
}
__device__ __forceinline__ float sigf(float x) {
    return fmaf(tanh_fast(0.5f * x), 0.5f, 0.5f);
}

__device__ __forceinline__ void fma2(unsigned long long& d, unsigned long long a,
                                     unsigned long long b) {
    asm("fma.rn.f32x2 %0, %1, %2, %0;" : "+l"(d) : "l"(a), "l"(b));
}
__device__ __forceinline__ void unpackf2(unsigned long long v, float& lo, float& hi) {
    asm("mov.b64 {%0, %1}, %2;" : "=f"(lo), "=f"(hi) : "l"(v));
}

// padded slot for h: half 1 (j>=32) shifted by 4 floats (16B) to dodge the
// 128B-apart same-bank aliasing of the two broadcast streams
#define HSLOT(j) ((j) + (((j) >> 5) << 2))

// ---------------- setup ----------------
__global__ void k_init() {
    int i = blockIdx.x * blockDim.x + threadIdx.x;
    if (i < NN) { g_deg_out[i] = 0; g_deg_in[i] = 0; g_cursor[i] = 0; }
}

__global__ void k_deg(const int* __restrict__ esrc, const int* __restrict__ edst) {
    int e = blockIdx.x * blockDim.x + threadIdx.x;
    if (e < NE) {
        atomicAdd(&g_deg_out[esrc[e]], 1);
        atomicAdd(&g_deg_in[edst[e]], 1);
    }
}

__global__ void k_norm() {
    int i = blockIdx.x * blockDim.x + threadIdx.x;
    if (i < NN) {
        int dout = g_deg_out[i], din = g_deg_in[i];
        g_nsrc[i] = (dout > 0) ? rsqrtf((float)dout) : 0.0f;
        g_ndst[i] = (din  > 0) ? rsqrtf((float)din)  : 0.0f;
    }
}

// ---------------- phase 1: per-node LSTM ----------------
// 512 threads, 16 warps. Warp w, lane l: half=l&1, q=(l>>1)&3, grp=l>>3.
// Gate row g = grp*64 + w*4 + q (half-row per lane, 16 f32x2 weight regs).
// After shfl_xor(1) half-combine, all 4 gate acts for unit j=w*4+q are in
// this warp -> 4 shfls gather I,F,G,O; c replicated across the 8 lanes that
// share j (identical inputs => identical results). Double-buffered h in
// shared => ONE __syncthreads per timestep. No act_sm, no serial tail.
__global__ void __launch_bounds__(512) k_lstm(
    const float* __restrict__ blob,
    const float* __restrict__ Wih,
    const float* __restrict__ bih,
    const float* __restrict__ Whh,
    const float* __restrict__ bhh)
{
    int node = blockIdx.x;
    int tid  = threadIdx.x;
    int wid  = tid >> 5;
    int lane = tid & 31;
    int half = lane & 1;
    int q    = (lane >> 1) & 3;
    int grp  = lane >> 3;
    int j    = wid * 4 + q;          // hidden unit this lane updates
    int g    = grp * 64 + j;         // gate row this lane's weights cover

    __shared__ __align__(16) float hf_sm[2][72];   // [buf][HSLOT(j)]
    __shared__ float x_sm[TT];

    // this half-row's 32 weights as 16 packed f32x2
    unsigned long long w[16];
    const ulonglong2* wp = (const ulonglong2*)
        (Whh + ((size_t)node * G4 + g) * HH + half * 32);
#pragma unroll
    for (int i = 0; i < 8; i++) {
        ulonglong2 v = wp[i];
        w[2 * i + 0] = v.x;
        w[2 * i + 1] = v.y;
    }
    float wx   = Wih[(size_t)node * G4 + g];
    float bias = bih[(size_t)node * G4 + g] + bhh[(size_t)node * G4 + g];
    float ns   = g_nsrc[node];

    // branchless activation constants: grp==2 -> tanh, else sigmoid
    float ascale = (grp == 2) ? 1.0f : 0.5f;
    float amul   = (grp == 2) ? 1.0f : 0.5f;
    float aadd   = (grp == 2) ? 0.0f : 0.5f;

    bool writer = (lane < 8) && (half == 0);   // grp==0, half==0 -> 4 lanes/warp
    int  slot   = HSLOT(j);

    if (tid < TT) x_sm[tid] = blob[node * TT + tid];
    float c = 0.0f;
    __syncthreads();

    __half* gH = (__half*)g_Hh;
    int src = lane & 7;   // lane holding (grp=0, my q, my half)

    // ---- t = 0: h = 0 ----
    {
        float gate = fmaf(wx, x_sm[0], bias);
        float act  = fmaf(tanh_fast(gate * ascale), amul, aadd);
        float I = __shfl_sync(FULL, act, src);
        float G = __shfl_sync(FULL, act, src + 16);
        float O = __shfl_sync(FULL, act, src + 24);
        c = I * G;
        float hv = O * tanh_fast(c);
        if (writer) {
            hf_sm[1][slot] = hv;
            gH[((size_t)0 * NN + node) * HH + j] = __float2half_rn(hv * ns);
        }
        __syncthreads();
    }

    for (int t = 1; t < TT; t++) {
        int rb = t & 1, wb = rb ^ 1;
        const ulonglong2* hp = (const ulonglong2*)(hf_sm[rb] + half * 36);
        unsigned long long acc0 = 0ull, acc1 = 0ull;   // f32x2 {0,0}
#pragma unroll
        for (int k = 0; k < 8; k++) {
            ulonglong2 hv = hp[k];
            fma2(acc0, hv.x, w[2 * k + 0]);
            fma2(acc1, hv.y, w[2 * k + 1]);
        }
        float a0, a1, a2, a3;
        unpackf2(acc0, a0, a1);
        unpackf2(acc1, a2, a3);
        float s = (a0 + a1) + (a2 + a3);
        s += __shfl_xor_sync(FULL, s, 1);              // combine half-rows

        float gate = fmaf(wx, x_sm[t], bias) + s;
        float act  = fmaf(tanh_fast(gate * ascale), amul, aadd);
        float I = __shfl_sync(FULL, act, src);
        float F = __shfl_sync(FULL, act, src + 8);
        float G = __shfl_sync(FULL, act, src + 16);
        float O = __shfl_sync(FULL, act, src + 24);
        c = fmaf(F, c, I * G);
        float hv = O * tanh_fast(c);
        if (writer) {
            hf_sm[wb][slot] = hv;
            gH[((size_t)t * NN + node) * HH + j] = __float2half_rn(hv * ns);
        }
        __syncthreads();
    }
}

// ---------------- scan: 1024 threads, 10 nodes/thread ----------------
__global__ void k_scan() {
    __shared__ int warp_tot[32];
    int tid = threadIdx.x;
    const int PER = 10;
    int start = tid * PER;
    int sum = 0;
#pragma unroll
    for (int i = 0; i < PER; i++) {
        int n = start + i;
        if (n < NN) sum += g_deg_in[n];
    }
    int lane = tid & 31, w = tid >> 5;
    int inc = sum;
#pragma unroll
    for (int off = 1; off < 32; off <<= 1) {
        int v = __shfl_up_sync(FULL, inc, off);
        if (lane >= off) inc += v;
    }
    if (lane == 31) warp_tot[w] = inc;
    __syncthreads();
    if (w == 0) {
        int v = warp_tot[lane];
#pragma unroll
        for (int off = 1; off < 32; off <<= 1) {
            int u = __shfl_up_sync(FULL, v, off);
            if (lane >= off) v += u;
        }
        warp_tot[lane] = v;
    }
    __syncthreads();
    int base = inc - sum + ((w > 0) ? warp_tot[w - 1] : 0);
    int run = base;
    for (int i = 0; i < PER; i++) {
        int n = start + i;
        if (n < NN) { g_offs[n] = run; run += g_deg_in[n]; }
    }
    if (tid == 1023) g_offs[NN] = base;
}

__global__ void k_scatter(const int* __restrict__ esrc, const int* __restrict__ edst) {
    int e = blockIdx.x * blockDim.x + threadIdx.x;
    if (e < NE) {
        int d = edst[e];
        int pos = g_offs[d] + atomicAdd(&g_cursor[d], 1);
        g_csr[pos] = esrc[e];
    }
}

// ---------------- phase 2: warp handles 4 nodes (as 2 pairs); fused gconv ----------------
template<int MODE>
__global__ __launch_bounds__(256) void k_gconv(
    const float* __restrict__ W,
    const float* __restrict__ b,
    const float* __restrict__ Wg2)
{
    __shared__ float Wsm[HH * HH];
    __shared__ float bsm[HH];
    __shared__ float w2sm[HH];
    __shared__ __align__(16) float aggsm[8][2][HH];

    int tid = threadIdx.x;
    int wp  = tid >> 5;
    int lane = tid & 31;
    int t = blockIdx.y;

    for (int i = tid; i < HH * HH; i += 256) Wsm[i] = W[i];
    if (tid < HH) {
        bsm[tid] = b[tid];
        if (MODE == 1) w2sm[tid] = Wg2[tid];
    }
    __syncthreads();

    const __half2* __restrict__ Xt =
        ((MODE == 0) ? g_Hh : g_Zh) + (size_t)t * NN * 32;

    for (int p = 0; p < 2; p++) {
        int nodeA = blockIdx.x * 32 + wp * 4 + 2 * p;
        int nodeB = nodeA + 1;

#pragma unroll
        for (int s = 0; s < 2; s++) {
            int node = nodeA + s;
            if (node < NN) {
                int rs = g_offs[node], re = g_offs[node + 1];
                float ax0 = 0.f, ay0 = 0.f, ax1 = 0.f, ay1 = 0.f;
                for (int base = rs; base < re; base += 32) {
                    int nloc = min(32, re - base);
                    int idx = (lane < nloc) ? g_csr[base + lane] : 0;
                    int j = 0;
                    for (; j + 4 <= nloc; j += 4) {
                        int s0 = __shfl_sync(FULL, idx, j + 0);
                        int s1 = __shfl_sync(FULL, idx, j + 1);
                        int s2 = __shfl_sync(FULL, idx, j + 2);
                        int s3 = __shfl_sync(FULL, idx, j + 3);
                        float2 v0 = __half22float2(Xt[(size_t)s0 * 32 + lane]);
                        float2 v1 = __half22float2(Xt[(size_t)s1 * 32 + lane]);
                        float2 v2 = __half22float2(Xt[(size_t)s2 * 32 + lane]);
                        float2 v3 = __half22float2(Xt[(size_t)s3 * 32 + lane]);
                        ax0 += v0.x + v1.x; ay0 += v0.y + v1.y;
                        ax1 += v2.x + v3.x; ay1 += v2.y + v3.y;
                    }
                    for (; j < nloc; j++) {
                        int sx = __shfl_sync(FULL, idx, j);
                        float2 v = __half22float2(Xt[(size_t)sx * 32 + lane]);
                        ax0 += v.x; ay0 += v.y;
                    }
                }
                float nd = g_ndst[node];
                aggsm[wp][s][2 * lane + 0] = (ax0 + ax1) * nd;
                aggsm[wp][s][2 * lane + 1] = (ay0 + ay1) * nd;
            }
        }
        __syncwarp();

        if (nodeA < NN) {
            bool haveB = (nodeB < NN);
            int d0 = 2 * lane;
            float za0 = bsm[d0], za1 = bsm[d0 + 1];
            float zb0 = za0, zb1 = za1;
            const float4* aA = (const float4*)aggsm[wp][0];
            const float4* aB = (const float4*)aggsm[wp][1];
#pragma unroll
            for (int k4 = 0; k4 < 16; k4++) {
                float4 a = aA[k4];
                float4 bb = aB[k4];
                int kb = k4 * 4;
                float2 w0 = ((const float2*)(Wsm + (kb + 0) * HH))[lane];
                float2 w1 = ((const float2*)(Wsm + (kb + 1) * HH))[lane];
                float2 w2 = ((const float2*)(Wsm + (kb + 2) * HH))[lane];
                float2 w3 = ((const float2*)(Wsm + (kb + 3) * HH))[lane];
                za0 = fmaf(a.x, w0.x, za0); za1 = fmaf(a.x, w0.y, za1);
                zb0 = fmaf(bb.x, w0.x, zb0); zb1 = fmaf(bb.x, w0.y, zb1);
                za0 = fmaf(a.y, w1.x, za0); za1 = fmaf(a.y, w1.y, za1);
                zb0 = fmaf(bb.y, w1.x, zb0); zb1 = fmaf(bb.y, w1.y, zb1);
                za0 = fmaf(a.z, w2.x, za0); za1 = fmaf(a.z, w2.y, za1);
                zb0 = fmaf(bb.z, w2.x, zb0); zb1 = fmaf(bb.z, w2.y, zb1);
                za0 = fmaf(a.w, w3.x, za0); za1 = fmaf(a.w, w3.y, za1);
                zb0 = fmaf(bb.w, w3.x, zb0); zb1 = fmaf(bb.w, w3.y, zb1);
            }

            float nsA = g_nsrc[nodeA];
            za0 = fmaxf(za0, 0.0f) * nsA;
            za1 = fmaxf(za1, 0.0f) * nsA;
            float nsB = haveB ? g_nsrc[nodeB] : 0.0f;
            zb0 = fmaxf(zb0, 0.0f) * nsB;
            zb1 = fmaxf(zb1, 0.0f) * nsB;

            if (MODE == 0) {
                g_Zh[((size_t)t * NN + nodeA) * 32 + lane] = __floats2half2_rn(za0, za1);
                if (haveB)
                    g_Zh[((size_t)t * NN + nodeB) * 32 + lane] = __floats2half2_rn(zb0, zb1);
            } else {
                float pa = za0 * w2sm[d0] + za1 * w2sm[d0 + 1];
                float pb = zb0 * w2sm[d0] + zb1 * w2sm[d0 + 1];
#pragma unroll
                for (int off = 16; off >= 1; off >>= 1) {
                    pa += __shfl_xor_sync(FULL, pa, off);
                    pb += __shfl_xor_sync(FULL, pb, off);
                }
                if (lane == 0) {
                    g_P[(size_t)nodeA * TT + t] = pa;
                    if (haveB) g_P[(size_t)nodeB * TT + t] = pb;
                }
            }
        }
        __syncwarp();
    }
}

// ---------------- final: warp-per-node, lane = t ----------------
__global__ __launch_bounds__(256) void k_final(float* __restrict__ out,
                                               const float* __restrict__ bg2) {
    int node = blockIdx.x * 8 + (threadIdx.x >> 5);
    int lane = threadIdx.x & 31;
    if (node >= NN) return;

    int rs = g_offs[node], re = g_offs[node + 1];
    float s0 = 0.f, s1 = 0.f, s2 = 0.f, s3 = 0.f;

    for (int base = rs; base < re; base += 32) {
        int nloc = min(32, re - base);
        int idx = (lane < nloc) ? g_csr[base + lane] : 0;
        int j = 0;
        for (; j + 4 <= nloc; j += 4) {
            int a0 = __shfl_sync(FULL, idx, j + 0);
            int a1 = __shfl_sync(FULL, idx, j + 1);
            int a2 = __shfl_sync(FULL, idx, j + 2);
            int a3 = __shfl_sync(FULL, idx, j + 3);
            s0 += g_P[(size_t)a0 * TT + lane];
            s1 += g_P[(size_t)a1 * TT + lane];
            s2 += g_P[(size_t)a2 * TT + lane];
            s3 += g_P[(size_t)a3 * TT + lane];
        }
        for (; j < nloc; j++) {
            int a = __shfl_sync(FULL, idx, j);
            s0 += g_P[(size_t)a * TT + lane];
        }
    }
    float s = (s0 + s1) + (s2 + s3);
    if (lane < TT)
        out[node * TT + lane] = g_ndst[node] * s + bg2[0];
}

// ---------------- launch ----------------
extern "C" void kernel_launch(void* const* d_in, const int* in_sizes, int n_in,
                              void* d_out, int out_size)
{
    const float* blob = (const float*)d_in[0];
    const float* Wih  = (const float*)d_in[1];
    const float* bih  = (const float*)d_in[2];
    const float* Whh  = (const float*)d_in[3];
    const float* bhh  = (const float*)d_in[4];
    const float* Wg0  = (const float*)d_in[5];
    const float* bg0  = (const float*)d_in[6];
    const float* Wg1  = (const float*)d_in[7];
    const float* bg1  = (const float*)d_in[8];
    const float* Wg2  = (const float*)d_in[9];
    const float* bg2  = (const float*)d_in[10];
    const int*   esrc = (const int*)d_in[11];
    const int*   edst = (const int*)d_in[12];
    float* out = (float*)d_out;

    k_init<<<(NN + 255) / 256, 256>>>();
    k_deg<<<(NE + 255) / 256, 256>>>(esrc, edst);
    k_norm<<<(NN + 255) / 256, 256>>>();

    // LSTM stays in the ncu capture slot
    k_lstm<<<NN, 512>>>(blob, Wih, bih, Whh, bhh);

    k_scan<<<1, 1024>>>();
    k_scatter<<<(NE + 255) / 256, 256>>>(esrc, edst);

    dim3 gg((NN + 31) / 32, TT);
    k_gconv<0><<<gg, 256>>>(Wg0, bg0, nullptr);
    k_gconv<1><<<gg, 256>>>(Wg1, bg1, Wg2);

    k_final<<<(NN + 7) / 8, 256>>>(out, bg2);
}